// round 4
// baseline (speedup 1.0000x reference)
#include <cuda_runtime.h>
#include <cstdint>

// LightGCN_75900662055226 — R4: pull SpMM with smem meta staging + 4x unrolled
// gathers (MLP), vectorized degree count, dinv folded into scan.

#define NUM_USERS 100000
#define NUM_ITEMS 50000
#define NN (NUM_USERS + NUM_ITEMS)   // 150000
#define EE 2000000
#define DD 64
#define NL 3

#define NB ((NN + 255) / 256)        // 586 scan blocks

__device__ int   g_ideg[NN];         // integer in-degree
__device__ float g_dinv[NN];         // 1/sqrt(deg)
__device__ int   g_bsum[NB];         // per-block degree sums
__device__ int   g_boff[NB];         // exclusive scan of block sums
__device__ int   g_rowptr[NN + 1];   // CSR row pointers (by dst)
__device__ int   g_fill[NN];         // fill cursors for binning
__device__ int2  g_csr[EE];          // (src, w-as-int-bits) sorted by dst
__device__ float g_x[2][NN * DD];    // ping-pong layer buffers

// ---------------------------------------------------------------------------

__global__ void k_zero_deg() {
    int i = blockIdx.x * blockDim.x + threadIdx.x;
    if (i < NN) g_ideg[i] = 0;
}

// 4 edges per thread via int4 loads (EE % 4 == 0).
__global__ void k_deg(const int4* __restrict__ dst4) {
    int i = blockIdx.x * blockDim.x + threadIdx.x;
    if (i < EE / 4) {
        int4 d = dst4[i];
        atomicAdd(&g_ideg[d.x], 1);
        atomicAdd(&g_ideg[d.y], 1);
        atomicAdd(&g_ideg[d.z], 1);
        atomicAdd(&g_ideg[d.w], 1);
    }
}

// --- 3-step exclusive scan of g_ideg -> g_rowptr (+ dinv fused in step 3) ---

__global__ void k_scan1() {                       // per-block reduce
    __shared__ int sh[256];
    int i = blockIdx.x * 256 + threadIdx.x;
    int v = (i < NN) ? g_ideg[i] : 0;
    sh[threadIdx.x] = v;
    __syncthreads();
    for (int s = 128; s > 0; s >>= 1) {
        if (threadIdx.x < s) sh[threadIdx.x] += sh[threadIdx.x + s];
        __syncthreads();
    }
    if (threadIdx.x == 0) g_bsum[blockIdx.x] = sh[0];
}

__global__ void k_scan2() {                       // single-block scan of block sums
    __shared__ int sh[1024];
    int i = threadIdx.x;
    int v = (i < NB) ? g_bsum[i] : 0;
    sh[i] = v;
    __syncthreads();
    for (int s = 1; s < 1024; s <<= 1) {          // inclusive Hillis-Steele
        int t = (i >= s) ? sh[i - s] : 0;
        __syncthreads();
        sh[i] += t;
        __syncthreads();
    }
    if (i < NB) g_boff[i] = sh[i] - v;            // exclusive
}

__global__ void k_scan3() {                       // per-block scan + offset + dinv
    __shared__ int sh[256];
    int i = blockIdx.x * 256 + threadIdx.x;
    int v = (i < NN) ? g_ideg[i] : 0;
    sh[threadIdx.x] = v;
    __syncthreads();
    for (int s = 1; s < 256; s <<= 1) {           // inclusive
        int t = (threadIdx.x >= s) ? sh[threadIdx.x - s] : 0;
        __syncthreads();
        sh[threadIdx.x] += t;
        __syncthreads();
    }
    if (i < NN) {
        int start = g_boff[blockIdx.x] + sh[threadIdx.x] - v;  // exclusive
        g_rowptr[i] = start;
        g_fill[i] = start;
        g_dinv[i] = (v > 0) ? rsqrtf((float)v) : 0.0f;
    }
    if (i == 0) g_rowptr[NN] = EE;
}

// --- bin edges into CSR (by dst), weight precomputed ------------------------

__global__ void k_fill(const int* __restrict__ src, const int* __restrict__ dst) {
    int e = blockIdx.x * blockDim.x + threadIdx.x;
    if (e >= EE) return;
    int s = src[e];
    int t = dst[e];
    float w = g_dinv[s] * g_dinv[t];
    int pos = atomicAdd(&g_fill[t], 1);
    g_csr[pos] = make_int2(s, __float_as_int(w));
}

// --- x0 = emb, out = emb ----------------------------------------------------

__global__ void k_init(const float4* __restrict__ emb, float4* __restrict__ out) {
    int i = blockIdx.x * blockDim.x + threadIdx.x;
    const int n4 = NN * DD / 4;
    if (i < n4) {
        float4 v = emb[i];
        reinterpret_cast<float4*>(g_x[0])[i] = v;
        out[i] = v;
    }
}

// --- pull-mode SpMM: one warp per dst row, lane owns one float2 column -----
// Meta staged in smem (LDS broadcast), gathers unrolled x4 for MLP.
// mode 0: out += acc; mode 1: out = (out + acc) * 0.25
__global__ void __launch_bounds__(256) k_pull(int cur, int mode,
                                              float2* __restrict__ out) {
    __shared__ int2 smeta[8][32];                 // 8 warps per 256-thread block
    int wslot = threadIdx.x >> 5;
    int row = (blockIdx.x * blockDim.x + threadIdx.x) >> 5;
    int lane = threadIdx.x & 31;
    if (row >= NN) return;

    int beg = g_rowptr[row];
    int end = g_rowptr[row + 1];

    const float2* __restrict__ xin = (const float2*)g_x[cur];
    float acx = 0.0f, acy = 0.0f;

    for (int base = beg; base < end; base += 32) {
        int e = base + lane;
        smeta[wslot][lane] = (e < end) ? g_csr[e] : make_int2(0, 0);
        __syncwarp();
        int cnt = min(32, end - base);

        int j = 0;
        for (; j + 4 <= cnt; j += 4) {
            int2 m0 = smeta[wslot][j + 0];
            int2 m1 = smeta[wslot][j + 1];
            int2 m2 = smeta[wslot][j + 2];
            int2 m3 = smeta[wslot][j + 3];
            float2 v0 = xin[m0.x * 32 + lane];
            float2 v1 = xin[m1.x * 32 + lane];
            float2 v2 = xin[m2.x * 32 + lane];
            float2 v3 = xin[m3.x * 32 + lane];
            float w0 = __int_as_float(m0.y);
            float w1 = __int_as_float(m1.y);
            float w2 = __int_as_float(m2.y);
            float w3 = __int_as_float(m3.y);
            acx += w0 * v0.x; acy += w0 * v0.y;
            acx += w1 * v1.x; acy += w1 * v1.y;
            acx += w2 * v2.x; acy += w2 * v2.y;
            acx += w3 * v3.x; acy += w3 * v3.y;
        }
        for (; j < cnt; ++j) {
            int2 m = smeta[wslot][j];
            float2 v = xin[m.x * 32 + lane];
            float w = __int_as_float(m.y);
            acx += w * v.x; acy += w * v.y;
        }
        __syncwarp();
    }

    int oidx = row * 32 + lane;
    ((float2*)g_x[cur ^ 1])[oidx] = make_float2(acx, acy);

    float2 o = out[oidx];
    if (mode == 0) {
        o.x += acx; o.y += acy;
    } else {
        o.x = (o.x + acx) * 0.25f;
        o.y = (o.y + acy) * 0.25f;
    }
    out[oidx] = o;
}

// ---------------------------------------------------------------------------

extern "C" void kernel_launch(void* const* d_in, const int* in_sizes, int n_in,
                              void* d_out, int out_size) {
    const int* edge = (const int*)d_in[0];      // [2, E] row-major
    const int* src = edge;
    const int* dst = edge + EE;
    const float* emb = (const float*)d_in[1];   // [N, 64]
    float* out = (float*)d_out;                 // [N, 64]

    const int T = 256;
    const int n4 = NN * DD / 4;

    k_zero_deg<<<(NN + T - 1) / T, T>>>();
    k_deg<<<(EE / 4 + T - 1) / T, T>>>((const int4*)dst);

    k_scan1<<<NB, 256>>>();
    k_scan2<<<1, 1024>>>();
    k_scan3<<<NB, 256>>>();

    k_fill<<<(EE + T - 1) / T, T>>>(src, dst);
    k_init<<<(n4 + T - 1) / T, T>>>((const float4*)emb, (float4*)out);

    int pull_blocks = (NN * 32 + T - 1) / T;    // one warp per row
    for (int l = 0; l < NL; ++l) {
        int cur = l & 1;
        int mode = (l == NL - 1) ? 1 : 0;
        k_pull<<<pull_blocks, T>>>(cur, mode, (float2*)out);
    }
    (void)in_sizes; (void)n_in; (void)out_size;
}

// round 5
// speedup vs baseline: 1.3336x; 1.3336x over previous
#include <cuda_runtime.h>
#include <cuda_fp16.h>
#include <cstdint>

// LightGCN_75900662055226 — R5: fp16 layer storage (fp32 accumulate),
// deferred accumulation (no per-layer out RMW), fused final epilogue.

#define NUM_USERS 100000
#define NUM_ITEMS 50000
#define NN (NUM_USERS + NUM_ITEMS)   // 150000
#define EE 2000000
#define DD 64
#define NL 3

#define NB ((NN + 255) / 256)        // 586 scan blocks

__device__ int    g_ideg[NN];        // integer in-degree
__device__ float  g_dinv[NN];        // 1/sqrt(deg)
__device__ int    g_bsum[NB];
__device__ int    g_boff[NB];
__device__ int    g_rowptr[NN + 1];  // CSR row pointers (by dst)
__device__ int    g_fill[NN];        // fill cursors
__device__ int2   g_csr[EE];         // (src, w-as-int-bits) sorted by dst
__device__ __half g_xh[3][NN * DD];  // x0(=emb), x1, x2 in fp16

// ---------------------------------------------------------------------------

__global__ void k_zero_deg() {
    int i = blockIdx.x * blockDim.x + threadIdx.x;
    if (i < NN) g_ideg[i] = 0;
}

__global__ void k_deg(const int4* __restrict__ dst4) {
    int i = blockIdx.x * blockDim.x + threadIdx.x;
    if (i < EE / 4) {
        int4 d = dst4[i];
        atomicAdd(&g_ideg[d.x], 1);
        atomicAdd(&g_ideg[d.y], 1);
        atomicAdd(&g_ideg[d.z], 1);
        atomicAdd(&g_ideg[d.w], 1);
    }
}

// --- 3-step exclusive scan of g_ideg -> g_rowptr (+ dinv fused) -------------

__global__ void k_scan1() {
    __shared__ int sh[256];
    int i = blockIdx.x * 256 + threadIdx.x;
    int v = (i < NN) ? g_ideg[i] : 0;
    sh[threadIdx.x] = v;
    __syncthreads();
    for (int s = 128; s > 0; s >>= 1) {
        if (threadIdx.x < s) sh[threadIdx.x] += sh[threadIdx.x + s];
        __syncthreads();
    }
    if (threadIdx.x == 0) g_bsum[blockIdx.x] = sh[0];
}

__global__ void k_scan2() {
    __shared__ int sh[1024];
    int i = threadIdx.x;
    int v = (i < NB) ? g_bsum[i] : 0;
    sh[i] = v;
    __syncthreads();
    for (int s = 1; s < 1024; s <<= 1) {
        int t = (i >= s) ? sh[i - s] : 0;
        __syncthreads();
        sh[i] += t;
        __syncthreads();
    }
    if (i < NB) g_boff[i] = sh[i] - v;
}

__global__ void k_scan3() {
    __shared__ int sh[256];
    int i = blockIdx.x * 256 + threadIdx.x;
    int v = (i < NN) ? g_ideg[i] : 0;
    sh[threadIdx.x] = v;
    __syncthreads();
    for (int s = 1; s < 256; s <<= 1) {
        int t = (threadIdx.x >= s) ? sh[threadIdx.x - s] : 0;
        __syncthreads();
        sh[threadIdx.x] += t;
        __syncthreads();
    }
    if (i < NN) {
        int start = g_boff[blockIdx.x] + sh[threadIdx.x] - v;
        g_rowptr[i] = start;
        g_fill[i] = start;
        g_dinv[i] = (v > 0) ? rsqrtf((float)v) : 0.0f;
    }
    if (i == 0) g_rowptr[NN] = EE;
}

// --- bin edges into CSR (by dst), weight precomputed, 4 edges/thread --------

__global__ void k_fill(const int4* __restrict__ src4, const int4* __restrict__ dst4) {
    int i = blockIdx.x * blockDim.x + threadIdx.x;
    if (i >= EE / 4) return;
    int4 s = src4[i];
    int4 t = dst4[i];
    {
        float w = g_dinv[s.x] * g_dinv[t.x];
        g_csr[atomicAdd(&g_fill[t.x], 1)] = make_int2(s.x, __float_as_int(w));
    }
    {
        float w = g_dinv[s.y] * g_dinv[t.y];
        g_csr[atomicAdd(&g_fill[t.y], 1)] = make_int2(s.y, __float_as_int(w));
    }
    {
        float w = g_dinv[s.z] * g_dinv[t.z];
        g_csr[atomicAdd(&g_fill[t.z], 1)] = make_int2(s.z, __float_as_int(w));
    }
    {
        float w = g_dinv[s.w] * g_dinv[t.w];
        g_csr[atomicAdd(&g_fill[t.w], 1)] = make_int2(s.w, __float_as_int(w));
    }
}

// --- x0 = emb (fp16) --------------------------------------------------------

__global__ void k_init(const float2* __restrict__ emb) {
    int i = blockIdx.x * blockDim.x + threadIdx.x;
    const int n2 = NN * DD / 2;
    if (i < n2) {
        float2 v = emb[i];
        reinterpret_cast<__half2*>(g_xh[0])[i] = __float22half2_rn(v);
    }
}

// --- pull-mode SpMM: one warp per dst row, lane owns one half2 column -------
// lin: which fp16 buffer to gather from. Writes g_xh[lin+1].
__global__ void __launch_bounds__(256) k_pull(int lin) {
    __shared__ int2 smeta[8][32];
    int wslot = threadIdx.x >> 5;
    int row = (blockIdx.x * blockDim.x + threadIdx.x) >> 5;
    int lane = threadIdx.x & 31;
    if (row >= NN) return;

    int beg = g_rowptr[row];
    int end = g_rowptr[row + 1];

    const __half2* __restrict__ xin = (const __half2*)g_xh[lin];
    float acx = 0.0f, acy = 0.0f;

    for (int base = beg; base < end; base += 32) {
        int e = base + lane;
        smeta[wslot][lane] = (e < end) ? g_csr[e] : make_int2(0, 0);
        __syncwarp();
        int cnt = min(32, end - base);

        int j = 0;
        for (; j + 4 <= cnt; j += 4) {
            int2 m0 = smeta[wslot][j + 0];
            int2 m1 = smeta[wslot][j + 1];
            int2 m2 = smeta[wslot][j + 2];
            int2 m3 = smeta[wslot][j + 3];
            float2 v0 = __half22float2(xin[m0.x * 32 + lane]);
            float2 v1 = __half22float2(xin[m1.x * 32 + lane]);
            float2 v2 = __half22float2(xin[m2.x * 32 + lane]);
            float2 v3 = __half22float2(xin[m3.x * 32 + lane]);
            float w0 = __int_as_float(m0.y);
            float w1 = __int_as_float(m1.y);
            float w2 = __int_as_float(m2.y);
            float w3 = __int_as_float(m3.y);
            acx += w0 * v0.x; acy += w0 * v0.y;
            acx += w1 * v1.x; acy += w1 * v1.y;
            acx += w2 * v2.x; acy += w2 * v2.y;
            acx += w3 * v3.x; acy += w3 * v3.y;
        }
        for (; j < cnt; ++j) {
            int2 m = smeta[wslot][j];
            float2 v = __half22float2(xin[m.x * 32 + lane]);
            float w = __int_as_float(m.y);
            acx += w * v.x; acy += w * v.y;
        }
        __syncwarp();
    }

    int oidx = row * 32 + lane;
    ((__half2*)g_xh[lin + 1])[oidx] = __float22half2_rn(make_float2(acx, acy));
}

// --- final layer: compute x3 in regs, fuse out = (emb + x1 + x2 + x3)/4 -----
__global__ void __launch_bounds__(256) k_pull_fin(const float2* __restrict__ emb,
                                                  float2* __restrict__ out) {
    __shared__ int2 smeta[8][32];
    int wslot = threadIdx.x >> 5;
    int row = (blockIdx.x * blockDim.x + threadIdx.x) >> 5;
    int lane = threadIdx.x & 31;
    if (row >= NN) return;

    int beg = g_rowptr[row];
    int end = g_rowptr[row + 1];

    const __half2* __restrict__ xin = (const __half2*)g_xh[2];
    float acx = 0.0f, acy = 0.0f;

    for (int base = beg; base < end; base += 32) {
        int e = base + lane;
        smeta[wslot][lane] = (e < end) ? g_csr[e] : make_int2(0, 0);
        __syncwarp();
        int cnt = min(32, end - base);

        int j = 0;
        for (; j + 4 <= cnt; j += 4) {
            int2 m0 = smeta[wslot][j + 0];
            int2 m1 = smeta[wslot][j + 1];
            int2 m2 = smeta[wslot][j + 2];
            int2 m3 = smeta[wslot][j + 3];
            float2 v0 = __half22float2(xin[m0.x * 32 + lane]);
            float2 v1 = __half22float2(xin[m1.x * 32 + lane]);
            float2 v2 = __half22float2(xin[m2.x * 32 + lane]);
            float2 v3 = __half22float2(xin[m3.x * 32 + lane]);
            float w0 = __int_as_float(m0.y);
            float w1 = __int_as_float(m1.y);
            float w2 = __int_as_float(m2.y);
            float w3 = __int_as_float(m3.y);
            acx += w0 * v0.x; acy += w0 * v0.y;
            acx += w1 * v1.x; acy += w1 * v1.y;
            acx += w2 * v2.x; acy += w2 * v2.y;
            acx += w3 * v3.x; acy += w3 * v3.y;
        }
        for (; j < cnt; ++j) {
            int2 m = smeta[wslot][j];
            float2 v = __half22float2(xin[m.x * 32 + lane]);
            float w = __int_as_float(m.y);
            acx += w * v.x; acy += w * v.y;
        }
        __syncwarp();
    }

    int oidx = row * 32 + lane;
    float2 e0 = emb[oidx];
    float2 x1 = __half22float2(((const __half2*)g_xh[1])[oidx]);
    float2 x2 = __half22float2(((const __half2*)g_xh[2])[oidx]);
    float2 o;
    o.x = (e0.x + x1.x + x2.x + acx) * 0.25f;
    o.y = (e0.y + x1.y + x2.y + acy) * 0.25f;
    out[oidx] = o;
}

// ---------------------------------------------------------------------------

extern "C" void kernel_launch(void* const* d_in, const int* in_sizes, int n_in,
                              void* d_out, int out_size) {
    const int* edge = (const int*)d_in[0];      // [2, E] row-major
    const int* src = edge;
    const int* dst = edge + EE;
    const float* emb = (const float*)d_in[1];   // [N, 64]
    float* out = (float*)d_out;                 // [N, 64]

    const int T = 256;
    const int n2 = NN * DD / 2;

    k_zero_deg<<<(NN + T - 1) / T, T>>>();
    k_deg<<<(EE / 4 + T - 1) / T, T>>>((const int4*)dst);

    k_scan1<<<NB, 256>>>();
    k_scan2<<<1, 1024>>>();
    k_scan3<<<NB, 256>>>();

    k_fill<<<(EE / 4 + T - 1) / T, T>>>((const int4*)src, (const int4*)dst);
    k_init<<<(n2 + T - 1) / T, T>>>((const float2*)emb);

    int pull_blocks = (NN * 32 + T - 1) / T;    // one warp per row
    k_pull<<<pull_blocks, T>>>(0);              // x1 = A x0
    k_pull<<<pull_blocks, T>>>(1);              // x2 = A x1
    k_pull_fin<<<pull_blocks, T>>>((const float2*)emb, (float2*)out);

    (void)in_sizes; (void)n_in; (void)out_size;
}

// round 7
// speedup vs baseline: 1.3651x; 1.0236x over previous
#include <cuda_runtime.h>
#include <cuda_fp16.h>
#include <cstdint>

// LightGCN_75900662055226 — R6 resubmit (infra failure last round):
// y-space formulation (y = dinv .* x) removes per-edge weights:
// src-only CSR (4B/edge), weightless fill, fused epilogue.

#define NUM_USERS 100000
#define NUM_ITEMS 50000
#define NN (NUM_USERS + NUM_ITEMS)   // 150000
#define EE 2000000
#define DD 64
#define NL 3

#define NB ((NN + 255) / 256)        // 586 scan blocks

__device__ int    g_ideg[NN];        // integer in-degree
__device__ float  g_dinv[NN];        // 1/sqrt(deg) (0 if deg==0)
__device__ int    g_bsum[NB];        // per-block degree sums
__device__ int    g_rowptr[NN + 1];  // CSR row pointers (by dst)
__device__ int    g_fill[NN];        // fill cursors
__device__ int    g_csr[EE];         // src only, sorted by dst
__device__ __half g_yh[3][NN * DD];  // y0, y1, y2 in fp16 (y = dinv .* x)

// ---------------------------------------------------------------------------

__global__ void k_zero_deg() {
    int i = blockIdx.x * blockDim.x + threadIdx.x;
    if (i < NN) g_ideg[i] = 0;
}

__global__ void k_deg(const int4* __restrict__ dst4) {
    int i = blockIdx.x * blockDim.x + threadIdx.x;
    if (i < EE / 4) {
        int4 d = dst4[i];
        atomicAdd(&g_ideg[d.x], 1);
        atomicAdd(&g_ideg[d.y], 1);
        atomicAdd(&g_ideg[d.z], 1);
        atomicAdd(&g_ideg[d.w], 1);
    }
}

// --- scan step 1: per-block degree sums -------------------------------------

__global__ void k_scan1() {
    __shared__ int sh[256];
    int i = blockIdx.x * 256 + threadIdx.x;
    int v = (i < NN) ? g_ideg[i] : 0;
    sh[threadIdx.x] = v;
    __syncthreads();
    for (int s = 128; s > 0; s >>= 1) {
        if (threadIdx.x < s) sh[threadIdx.x] += sh[threadIdx.x + s];
        __syncthreads();
    }
    if (threadIdx.x == 0) g_bsum[blockIdx.x] = sh[0];
}

// --- scan step 2: block prefix (self-computed) + local scan + dinv ----------

__global__ void k_scan3() {
    __shared__ int sh[256];
    __shared__ int blk_prefix;

    // prefix = sum of g_bsum[0 .. blockIdx.x)
    int acc = 0;
    for (int j = threadIdx.x; j < blockIdx.x; j += 256) acc += g_bsum[j];
    sh[threadIdx.x] = acc;
    __syncthreads();
    for (int s = 128; s > 0; s >>= 1) {
        if (threadIdx.x < s) sh[threadIdx.x] += sh[threadIdx.x + s];
        __syncthreads();
    }
    if (threadIdx.x == 0) blk_prefix = sh[0];
    __syncthreads();

    // local inclusive scan of degrees
    int i = blockIdx.x * 256 + threadIdx.x;
    int v = (i < NN) ? g_ideg[i] : 0;
    sh[threadIdx.x] = v;
    __syncthreads();
    for (int s = 1; s < 256; s <<= 1) {
        int t = (threadIdx.x >= s) ? sh[threadIdx.x - s] : 0;
        __syncthreads();
        sh[threadIdx.x] += t;
        __syncthreads();
    }
    if (i < NN) {
        int start = blk_prefix + sh[threadIdx.x] - v;   // exclusive
        g_rowptr[i] = start;
        g_fill[i] = start;
        g_dinv[i] = (v > 0) ? rsqrtf((float)v) : 0.0f;
    }
    if (i == 0) g_rowptr[NN] = EE;
}

// --- bin edges into src-only CSR (by dst), 4 edges/thread -------------------

__global__ void k_fill(const int4* __restrict__ src4, const int4* __restrict__ dst4) {
    int i = blockIdx.x * blockDim.x + threadIdx.x;
    if (i >= EE / 4) return;
    int4 s = src4[i];
    int4 t = dst4[i];
    g_csr[atomicAdd(&g_fill[t.x], 1)] = s.x;
    g_csr[atomicAdd(&g_fill[t.y], 1)] = s.y;
    g_csr[atomicAdd(&g_fill[t.z], 1)] = s.z;
    g_csr[atomicAdd(&g_fill[t.w], 1)] = s.w;
}

// --- y0 = dinv .* emb (fp16) ------------------------------------------------

__global__ void k_init(const float2* __restrict__ emb) {
    int i = blockIdx.x * blockDim.x + threadIdx.x;   // half2 index
    const int n2 = NN * DD / 2;
    if (i < n2) {
        int node = i >> 5;                           // 32 half2 per node
        float di = g_dinv[node];
        float2 v = emb[i];
        v.x *= di; v.y *= di;
        reinterpret_cast<__half2*>(g_yh[0])[i] = __float22half2_rn(v);
    }
}

// --- pull: s_t = sum y[src]; y_next[t] = dinv[t]^2 * s_t --------------------

__global__ void __launch_bounds__(256) k_pull(int lin) {
    __shared__ int ssrc[8][32];
    int wslot = threadIdx.x >> 5;
    int row = (blockIdx.x * blockDim.x + threadIdx.x) >> 5;
    int lane = threadIdx.x & 31;
    if (row >= NN) return;

    int beg = g_rowptr[row];
    int end = g_rowptr[row + 1];

    const __half2* __restrict__ xin = (const __half2*)g_yh[lin];
    float acx = 0.0f, acy = 0.0f;

    for (int base = beg; base < end; base += 32) {
        int e = base + lane;
        ssrc[wslot][lane] = (e < end) ? g_csr[e] : 0;
        __syncwarp();
        int cnt = min(32, end - base);

        int j = 0;
        for (; j + 4 <= cnt; j += 4) {
            int s0 = ssrc[wslot][j + 0];
            int s1 = ssrc[wslot][j + 1];
            int s2 = ssrc[wslot][j + 2];
            int s3 = ssrc[wslot][j + 3];
            float2 v0 = __half22float2(xin[s0 * 32 + lane]);
            float2 v1 = __half22float2(xin[s1 * 32 + lane]);
            float2 v2 = __half22float2(xin[s2 * 32 + lane]);
            float2 v3 = __half22float2(xin[s3 * 32 + lane]);
            acx += v0.x + v1.x + v2.x + v3.x;
            acy += v0.y + v1.y + v2.y + v3.y;
        }
        for (; j < cnt; ++j) {
            float2 v = __half22float2(xin[ssrc[wslot][j] * 32 + lane]);
            acx += v.x; acy += v.y;
        }
        __syncwarp();
    }

    float di = g_dinv[row];
    float sc = di * di;
    int oidx = row * 32 + lane;
    ((__half2*)g_yh[lin + 1])[oidx] =
        __float22half2_rn(make_float2(acx * sc, acy * sc));
}

// --- final: x3 = dinv*s3; out = (emb + (y1+y2)*sqrt(deg) + x3) / 4 ---------

__global__ void __launch_bounds__(256) k_pull_fin(const float2* __restrict__ emb,
                                                  float2* __restrict__ out) {
    __shared__ int ssrc[8][32];
    int wslot = threadIdx.x >> 5;
    int row = (blockIdx.x * blockDim.x + threadIdx.x) >> 5;
    int lane = threadIdx.x & 31;
    if (row >= NN) return;

    int beg = g_rowptr[row];
    int end = g_rowptr[row + 1];

    const __half2* __restrict__ xin = (const __half2*)g_yh[2];
    float acx = 0.0f, acy = 0.0f;

    for (int base = beg; base < end; base += 32) {
        int e = base + lane;
        ssrc[wslot][lane] = (e < end) ? g_csr[e] : 0;
        __syncwarp();
        int cnt = min(32, end - base);

        int j = 0;
        for (; j + 4 <= cnt; j += 4) {
            int s0 = ssrc[wslot][j + 0];
            int s1 = ssrc[wslot][j + 1];
            int s2 = ssrc[wslot][j + 2];
            int s3 = ssrc[wslot][j + 3];
            float2 v0 = __half22float2(xin[s0 * 32 + lane]);
            float2 v1 = __half22float2(xin[s1 * 32 + lane]);
            float2 v2 = __half22float2(xin[s2 * 32 + lane]);
            float2 v3 = __half22float2(xin[s3 * 32 + lane]);
            acx += v0.x + v1.x + v2.x + v3.x;
            acy += v0.y + v1.y + v2.y + v3.y;
        }
        for (; j < cnt; ++j) {
            float2 v = __half22float2(xin[ssrc[wslot][j] * 32 + lane]);
            acx += v.x; acy += v.y;
        }
        __syncwarp();
    }

    float di = g_dinv[row];
    float sq = (di > 0.0f) ? (1.0f / di) : 0.0f;   // sqrt(deg)
    int oidx = row * 32 + lane;

    float2 e0 = emb[oidx];
    float2 y1 = __half22float2(((const __half2*)g_yh[1])[oidx]);
    float2 y2 = __half22float2(((const __half2*)g_yh[2])[oidx]);
    float2 o;
    o.x = (e0.x + (y1.x + y2.x) * sq + di * acx) * 0.25f;
    o.y = (e0.y + (y1.y + y2.y) * sq + di * acy) * 0.25f;
    out[oidx] = o;
}

// ---------------------------------------------------------------------------

extern "C" void kernel_launch(void* const* d_in, const int* in_sizes, int n_in,
                              void* d_out, int out_size) {
    const int* edge = (const int*)d_in[0];      // [2, E] row-major
    const int* src = edge;
    const int* dst = edge + EE;
    const float* emb = (const float*)d_in[1];   // [N, 64]
    float* out = (float*)d_out;                 // [N, 64]

    const int T = 256;
    const int n2 = NN * DD / 2;

    k_zero_deg<<<(NN + T - 1) / T, T>>>();
    k_deg<<<(EE / 4 + T - 1) / T, T>>>((const int4*)dst);

    k_scan1<<<NB, 256>>>();
    k_scan3<<<NB, 256>>>();

    k_fill<<<(EE / 4 + T - 1) / T, T>>>((const int4*)src, (const int4*)dst);
    k_init<<<(n2 + T - 1) / T, T>>>((const float2*)emb);

    int pull_blocks = (NN * 32 + T - 1) / T;    // one warp per row
    k_pull<<<pull_blocks, T>>>(0);              // y1
    k_pull<<<pull_blocks, T>>>(1);              // y2
    k_pull_fin<<<pull_blocks, T>>>((const float2*)emb, (float2*)out);

    (void)in_sizes; (void)n_in; (void)out_size;
}

// round 9
// speedup vs baseline: 1.3921x; 1.0198x over previous
#include <cuda_runtime.h>
#include <cuda_fp16.h>
#include <cstdint>

// LightGCN_75900662055226 — R9: atomic-free CSR fill (occ indices recycled
// from degree-pass atomicAdd returns), globals referenced device-side only.

#define NUM_USERS 100000
#define NUM_ITEMS 50000
#define NN (NUM_USERS + NUM_ITEMS)   // 150000
#define EE 2000000
#define DD 64
#define NL 3

#define NB ((NN + 255) / 256)        // 586 scan blocks

__device__ int    g_ideg[NN];        // integer in-degree
__device__ float  g_dinv[NN];        // 1/sqrt(deg) (0 if deg==0)
__device__ int    g_bsum[NB];        // per-block degree sums
__device__ int    g_rowptr[NN + 1];  // CSR row pointers (by dst)
__device__ int    g_occ[EE];         // per-edge occurrence index within dst row
__device__ int    g_csr[EE];         // src only, sorted by dst
__device__ __half g_yh[3][NN * DD];  // y0, y1, y2 in fp16 (y = dinv .* x)

// ---------------------------------------------------------------------------

__global__ void k_zero_deg() {
    int i = blockIdx.x * blockDim.x + threadIdx.x;
    if (i < NN) g_ideg[i] = 0;
}

// Degree count; atomicAdd's return = occurrence index, saved to g_occ.
__global__ void k_deg_occ(const int4* __restrict__ dst4) {
    int i = blockIdx.x * blockDim.x + threadIdx.x;
    if (i < EE / 4) {
        int4 d = dst4[i];
        int4 o;
        o.x = atomicAdd(&g_ideg[d.x], 1);
        o.y = atomicAdd(&g_ideg[d.y], 1);
        o.z = atomicAdd(&g_ideg[d.z], 1);
        o.w = atomicAdd(&g_ideg[d.w], 1);
        reinterpret_cast<int4*>(g_occ)[i] = o;
    }
}

// --- scan step 1: per-block degree sums -------------------------------------

__global__ void k_scan1() {
    __shared__ int sh[256];
    int i = blockIdx.x * 256 + threadIdx.x;
    int v = (i < NN) ? g_ideg[i] : 0;
    sh[threadIdx.x] = v;
    __syncthreads();
    for (int s = 128; s > 0; s >>= 1) {
        if (threadIdx.x < s) sh[threadIdx.x] += sh[threadIdx.x + s];
        __syncthreads();
    }
    if (threadIdx.x == 0) g_bsum[blockIdx.x] = sh[0];
}

// --- scan step 2: block prefix (self-computed) + local scan + dinv ----------

__global__ void k_scan3() {
    __shared__ int sh[256];
    __shared__ int blk_prefix;

    // prefix = sum of g_bsum[0 .. blockIdx.x)
    int acc = 0;
    for (int j = threadIdx.x; j < blockIdx.x; j += 256) acc += g_bsum[j];
    sh[threadIdx.x] = acc;
    __syncthreads();
    for (int s = 128; s > 0; s >>= 1) {
        if (threadIdx.x < s) sh[threadIdx.x] += sh[threadIdx.x + s];
        __syncthreads();
    }
    if (threadIdx.x == 0) blk_prefix = sh[0];
    __syncthreads();

    // local inclusive scan of degrees
    int i = blockIdx.x * 256 + threadIdx.x;
    int v = (i < NN) ? g_ideg[i] : 0;
    sh[threadIdx.x] = v;
    __syncthreads();
    for (int s = 1; s < 256; s <<= 1) {
        int t = (threadIdx.x >= s) ? sh[threadIdx.x - s] : 0;
        __syncthreads();
        sh[threadIdx.x] += t;
        __syncthreads();
    }
    if (i < NN) {
        int start = blk_prefix + sh[threadIdx.x] - v;   // exclusive
        g_rowptr[i] = start;
        g_dinv[i] = (v > 0) ? rsqrtf((float)v) : 0.0f;
    }
    if (i == 0) g_rowptr[NN] = EE;
}

// --- atomic-free CSR fill: slot = rowptr[dst] + occ[e] ----------------------

__global__ void k_fill(const int4* __restrict__ src4, const int4* __restrict__ dst4) {
    int i = blockIdx.x * blockDim.x + threadIdx.x;
    if (i >= EE / 4) return;
    int4 s = src4[i];
    int4 t = dst4[i];
    int4 o = reinterpret_cast<const int4*>(g_occ)[i];
    g_csr[g_rowptr[t.x] + o.x] = s.x;
    g_csr[g_rowptr[t.y] + o.y] = s.y;
    g_csr[g_rowptr[t.z] + o.z] = s.z;
    g_csr[g_rowptr[t.w] + o.w] = s.w;
}

// --- y0 = dinv .* emb (fp16) ------------------------------------------------

__global__ void k_init(const float2* __restrict__ emb) {
    int i = blockIdx.x * blockDim.x + threadIdx.x;   // half2 index
    const int n2 = NN * DD / 2;
    if (i < n2) {
        int node = i >> 5;                           // 32 half2 per node
        float di = g_dinv[node];
        float2 v = emb[i];
        v.x *= di; v.y *= di;
        reinterpret_cast<__half2*>(g_yh[0])[i] = __float22half2_rn(v);
    }
}

// --- pull: s_t = sum y[src]; y_next[t] = dinv[t]^2 * s_t --------------------

__global__ void __launch_bounds__(256) k_pull(int lin) {
    __shared__ int ssrc[8][32];
    int wslot = threadIdx.x >> 5;
    int row = (blockIdx.x * blockDim.x + threadIdx.x) >> 5;
    int lane = threadIdx.x & 31;
    if (row >= NN) return;

    int beg = g_rowptr[row];
    int end = g_rowptr[row + 1];

    const __half2* __restrict__ xin = (const __half2*)g_yh[lin];
    float acx = 0.0f, acy = 0.0f;

    for (int base = beg; base < end; base += 32) {
        int e = base + lane;
        ssrc[wslot][lane] = (e < end) ? g_csr[e] : 0;
        __syncwarp();
        int cnt = min(32, end - base);

        int j = 0;
        for (; j + 4 <= cnt; j += 4) {
            int s0 = ssrc[wslot][j + 0];
            int s1 = ssrc[wslot][j + 1];
            int s2 = ssrc[wslot][j + 2];
            int s3 = ssrc[wslot][j + 3];
            float2 v0 = __half22float2(xin[s0 * 32 + lane]);
            float2 v1 = __half22float2(xin[s1 * 32 + lane]);
            float2 v2 = __half22float2(xin[s2 * 32 + lane]);
            float2 v3 = __half22float2(xin[s3 * 32 + lane]);
            acx += v0.x + v1.x + v2.x + v3.x;
            acy += v0.y + v1.y + v2.y + v3.y;
        }
        for (; j < cnt; ++j) {
            float2 v = __half22float2(xin[ssrc[wslot][j] * 32 + lane]);
            acx += v.x; acy += v.y;
        }
        __syncwarp();
    }

    float di = g_dinv[row];
    float sc = di * di;
    int oidx = row * 32 + lane;
    ((__half2*)g_yh[lin + 1])[oidx] =
        __float22half2_rn(make_float2(acx * sc, acy * sc));
}

// --- final: x3 = dinv*s3; out = (emb + (y1+y2)*sqrt(deg) + x3) / 4 ---------

__global__ void __launch_bounds__(256) k_pull_fin(const float2* __restrict__ emb,
                                                  float2* __restrict__ out) {
    __shared__ int ssrc[8][32];
    int wslot = threadIdx.x >> 5;
    int row = (blockIdx.x * blockDim.x + threadIdx.x) >> 5;
    int lane = threadIdx.x & 31;
    if (row >= NN) return;

    int beg = g_rowptr[row];
    int end = g_rowptr[row + 1];

    const __half2* __restrict__ xin = (const __half2*)g_yh[2];
    float acx = 0.0f, acy = 0.0f;

    for (int base = beg; base < end; base += 32) {
        int e = base + lane;
        ssrc[wslot][lane] = (e < end) ? g_csr[e] : 0;
        __syncwarp();
        int cnt = min(32, end - base);

        int j = 0;
        for (; j + 4 <= cnt; j += 4) {
            int s0 = ssrc[wslot][j + 0];
            int s1 = ssrc[wslot][j + 1];
            int s2 = ssrc[wslot][j + 2];
            int s3 = ssrc[wslot][j + 3];
            float2 v0 = __half22float2(xin[s0 * 32 + lane]);
            float2 v1 = __half22float2(xin[s1 * 32 + lane]);
            float2 v2 = __half22float2(xin[s2 * 32 + lane]);
            float2 v3 = __half22float2(xin[s3 * 32 + lane]);
            acx += v0.x + v1.x + v2.x + v3.x;
            acy += v0.y + v1.y + v2.y + v3.y;
        }
        for (; j < cnt; ++j) {
            float2 v = __half22float2(xin[ssrc[wslot][j] * 32 + lane]);
            acx += v.x; acy += v.y;
        }
        __syncwarp();
    }

    float di = g_dinv[row];
    float sq = (di > 0.0f) ? (1.0f / di) : 0.0f;   // sqrt(deg)
    int oidx = row * 32 + lane;

    float2 e0 = emb[oidx];
    float2 y1 = __half22float2(((const __half2*)g_yh[1])[oidx]);
    float2 y2 = __half22float2(((const __half2*)g_yh[2])[oidx]);
    float2 o;
    o.x = (e0.x + (y1.x + y2.x) * sq + di * acx) * 0.25f;
    o.y = (e0.y + (y1.y + y2.y) * sq + di * acy) * 0.25f;
    out[oidx] = o;
}

// ---------------------------------------------------------------------------

extern "C" void kernel_launch(void* const* d_in, const int* in_sizes, int n_in,
                              void* d_out, int out_size) {
    const int* edge = (const int*)d_in[0];      // [2, E] row-major
    const int* src = edge;
    const int* dst = edge + EE;
    const float* emb = (const float*)d_in[1];   // [N, 64]
    float* out = (float*)d_out;                 // [N, 64]

    const int T = 256;
    const int n2 = NN * DD / 2;

    k_zero_deg<<<(NN + T - 1) / T, T>>>();
    k_deg_occ<<<(EE / 4 + T - 1) / T, T>>>((const int4*)dst);

    k_scan1<<<NB, 256>>>();
    k_scan3<<<NB, 256>>>();

    k_fill<<<(EE / 4 + T - 1) / T, T>>>((const int4*)src, (const int4*)dst);
    k_init<<<(n2 + T - 1) / T, T>>>((const float2*)emb);

    int pull_blocks = (NN * 32 + T - 1) / T;    // one warp per row
    k_pull<<<pull_blocks, T>>>(0);              // y1
    k_pull<<<pull_blocks, T>>>(1);              // y2
    k_pull_fin<<<pull_blocks, T>>>((const float2*)emb, (float2*)out);

    (void)in_sizes; (void)n_in; (void)out_size;
}

// round 10
// speedup vs baseline: 1.4472x; 1.0396x over previous
#include <cuda_runtime.h>
#include <cuda_fp16.h>
#include <cstdint>

// LightGCN_75900662055226 — R10: prep consolidation. memset for deg-zero,
// fused fill+init kernel, ushort occ. Pulls unchanged (at LTS traffic floor).

#define NUM_USERS 100000
#define NUM_ITEMS 50000
#define NN (NUM_USERS + NUM_ITEMS)   // 150000
#define EE 2000000
#define DD 64
#define NL 3

#define NB ((NN + 255) / 256)        // 586 scan blocks

__device__ int            g_ideg[NN];       // integer in-degree
__device__ float          g_dinv[NN];       // 1/sqrt(deg) (0 if deg==0)
__device__ int            g_bsum[NB];       // per-block degree sums
__device__ int            g_rowptr[NN + 1]; // CSR row pointers (by dst)
__device__ unsigned short g_occ[EE];        // per-edge occurrence index in dst row
__device__ int            g_csr[EE];        // src only, sorted by dst
__device__ __half         g_yh[3][NN * DD]; // y0, y1, y2 (y = dinv .* x)

// ---------------------------------------------------------------------------

// Degree count; atomicAdd's return = occurrence index (fits in ushort).
__global__ void k_deg_occ(const int4* __restrict__ dst4) {
    int i = blockIdx.x * blockDim.x + threadIdx.x;
    if (i < EE / 4) {
        int4 d = dst4[i];
        ushort4 o;
        o.x = (unsigned short)atomicAdd(&g_ideg[d.x], 1);
        o.y = (unsigned short)atomicAdd(&g_ideg[d.y], 1);
        o.z = (unsigned short)atomicAdd(&g_ideg[d.z], 1);
        o.w = (unsigned short)atomicAdd(&g_ideg[d.w], 1);
        reinterpret_cast<ushort4*>(g_occ)[i] = o;
    }
}

// --- scan step 1: per-block degree sums -------------------------------------

__global__ void k_scan1() {
    __shared__ int sh[256];
    int i = blockIdx.x * 256 + threadIdx.x;
    int v = (i < NN) ? g_ideg[i] : 0;
    sh[threadIdx.x] = v;
    __syncthreads();
    for (int s = 128; s > 0; s >>= 1) {
        if (threadIdx.x < s) sh[threadIdx.x] += sh[threadIdx.x + s];
        __syncthreads();
    }
    if (threadIdx.x == 0) g_bsum[blockIdx.x] = sh[0];
}

// --- scan step 2: block prefix (self-computed) + local scan + dinv ----------

__global__ void k_scan3() {
    __shared__ int sh[256];
    __shared__ int blk_prefix;

    int acc = 0;
    for (int j = threadIdx.x; j < blockIdx.x; j += 256) acc += g_bsum[j];
    sh[threadIdx.x] = acc;
    __syncthreads();
    for (int s = 128; s > 0; s >>= 1) {
        if (threadIdx.x < s) sh[threadIdx.x] += sh[threadIdx.x + s];
        __syncthreads();
    }
    if (threadIdx.x == 0) blk_prefix = sh[0];
    __syncthreads();

    int i = blockIdx.x * 256 + threadIdx.x;
    int v = (i < NN) ? g_ideg[i] : 0;
    sh[threadIdx.x] = v;
    __syncthreads();
    for (int s = 1; s < 256; s <<= 1) {
        int t = (threadIdx.x >= s) ? sh[threadIdx.x - s] : 0;
        __syncthreads();
        sh[threadIdx.x] += t;
        __syncthreads();
    }
    if (i < NN) {
        int start = blk_prefix + sh[threadIdx.x] - v;   // exclusive
        g_rowptr[i] = start;
        g_dinv[i] = (v > 0) ? rsqrtf((float)v) : 0.0f;
    }
    if (i == 0) g_rowptr[NN] = EE;
}

// --- fused: CSR fill (first FILL_BLOCKS) + y0 init (rest) -------------------
// fill: slot = rowptr[dst] + occ[e], zero atomics.
// init: y0 = dinv .* emb, float4 -> 2x half2 per thread.

#define FILL_BLOCKS ((EE / 4 + 255) / 256)          // 1954
#define INIT_N4 (NN * DD / 4)                       // 2.4M float4
#define INIT_BLOCKS ((INIT_N4 + 255) / 256)         // 9375

__global__ void k_fill_init(const int4* __restrict__ src4,
                            const int4* __restrict__ dst4,
                            const float4* __restrict__ emb4) {
    if (blockIdx.x < FILL_BLOCKS) {
        int i = blockIdx.x * blockDim.x + threadIdx.x;
        if (i >= EE / 4) return;
        int4 s = src4[i];
        int4 t = dst4[i];
        ushort4 o = reinterpret_cast<const ushort4*>(g_occ)[i];
        g_csr[g_rowptr[t.x] + o.x] = s.x;
        g_csr[g_rowptr[t.y] + o.y] = s.y;
        g_csr[g_rowptr[t.z] + o.z] = s.z;
        g_csr[g_rowptr[t.w] + o.w] = s.w;
    } else {
        int i = (blockIdx.x - FILL_BLOCKS) * blockDim.x + threadIdx.x;
        if (i >= INIT_N4) return;
        int node = i >> 4;                          // 16 float4 per node row
        float di = g_dinv[node];
        float4 v = emb4[i];
        __half2 h0 = __float22half2_rn(make_float2(v.x * di, v.y * di));
        __half2 h1 = __float22half2_rn(make_float2(v.z * di, v.w * di));
        __half2* yo = reinterpret_cast<__half2*>(g_yh[0]);
        yo[i * 2 + 0] = h0;
        yo[i * 2 + 1] = h1;
    }
}

// --- pull: s_t = sum y[src]; y_next[t] = dinv[t]^2 * s_t --------------------

__global__ void __launch_bounds__(256) k_pull(int lin) {
    __shared__ int ssrc[8][32];
    int wslot = threadIdx.x >> 5;
    int row = (blockIdx.x * blockDim.x + threadIdx.x) >> 5;
    int lane = threadIdx.x & 31;
    if (row >= NN) return;

    int beg = g_rowptr[row];
    int end = g_rowptr[row + 1];

    const __half2* __restrict__ xin = (const __half2*)g_yh[lin];
    float acx = 0.0f, acy = 0.0f;

    for (int base = beg; base < end; base += 32) {
        int e = base + lane;
        ssrc[wslot][lane] = (e < end) ? g_csr[e] : 0;
        __syncwarp();
        int cnt = min(32, end - base);

        int j = 0;
        for (; j + 4 <= cnt; j += 4) {
            int s0 = ssrc[wslot][j + 0];
            int s1 = ssrc[wslot][j + 1];
            int s2 = ssrc[wslot][j + 2];
            int s3 = ssrc[wslot][j + 3];
            float2 v0 = __half22float2(xin[s0 * 32 + lane]);
            float2 v1 = __half22float2(xin[s1 * 32 + lane]);
            float2 v2 = __half22float2(xin[s2 * 32 + lane]);
            float2 v3 = __half22float2(xin[s3 * 32 + lane]);
            acx += v0.x + v1.x + v2.x + v3.x;
            acy += v0.y + v1.y + v2.y + v3.y;
        }
        for (; j < cnt; ++j) {
            float2 v = __half22float2(xin[ssrc[wslot][j] * 32 + lane]);
            acx += v.x; acy += v.y;
        }
        __syncwarp();
    }

    float di = g_dinv[row];
    float sc = di * di;
    int oidx = row * 32 + lane;
    ((__half2*)g_yh[lin + 1])[oidx] =
        __float22half2_rn(make_float2(acx * sc, acy * sc));
}

// --- final: x3 = dinv*s3; out = (emb + (y1+y2)*sqrt(deg) + x3) / 4 ---------

__global__ void __launch_bounds__(256) k_pull_fin(const float2* __restrict__ emb,
                                                  float2* __restrict__ out) {
    __shared__ int ssrc[8][32];
    int wslot = threadIdx.x >> 5;
    int row = (blockIdx.x * blockDim.x + threadIdx.x) >> 5;
    int lane = threadIdx.x & 31;
    if (row >= NN) return;

    int beg = g_rowptr[row];
    int end = g_rowptr[row + 1];

    const __half2* __restrict__ xin = (const __half2*)g_yh[2];
    float acx = 0.0f, acy = 0.0f;

    for (int base = beg; base < end; base += 32) {
        int e = base + lane;
        ssrc[wslot][lane] = (e < end) ? g_csr[e] : 0;
        __syncwarp();
        int cnt = min(32, end - base);

        int j = 0;
        for (; j + 4 <= cnt; j += 4) {
            int s0 = ssrc[wslot][j + 0];
            int s1 = ssrc[wslot][j + 1];
            int s2 = ssrc[wslot][j + 2];
            int s3 = ssrc[wslot][j + 3];
            float2 v0 = __half22float2(xin[s0 * 32 + lane]);
            float2 v1 = __half22float2(xin[s1 * 32 + lane]);
            float2 v2 = __half22float2(xin[s2 * 32 + lane]);
            float2 v3 = __half22float2(xin[s3 * 32 + lane]);
            acx += v0.x + v1.x + v2.x + v3.x;
            acy += v0.y + v1.y + v2.y + v3.y;
        }
        for (; j < cnt; ++j) {
            float2 v = __half22float2(xin[ssrc[wslot][j] * 32 + lane]);
            acx += v.x; acy += v.y;
        }
        __syncwarp();
    }

    float di = g_dinv[row];
    float sq = (di > 0.0f) ? (1.0f / di) : 0.0f;   // sqrt(deg)
    int oidx = row * 32 + lane;

    float2 e0 = emb[oidx];
    float2 y1 = __half22float2(((const __half2*)g_yh[1])[oidx]);
    float2 y2 = __half22float2(((const __half2*)g_yh[2])[oidx]);
    float2 o;
    o.x = (e0.x + (y1.x + y2.x) * sq + di * acx) * 0.25f;
    o.y = (e0.y + (y1.y + y2.y) * sq + di * acy) * 0.25f;
    out[oidx] = o;
}

// ---------------------------------------------------------------------------

extern "C" void kernel_launch(void* const* d_in, const int* in_sizes, int n_in,
                              void* d_out, int out_size) {
    const int* edge = (const int*)d_in[0];      // [2, E] row-major
    const int* src = edge;
    const int* dst = edge + EE;
    const float* emb = (const float*)d_in[1];   // [N, 64]
    float* out = (float*)d_out;                 // [N, 64]

    const int T = 256;

    void* ideg_ptr = nullptr;
    cudaGetSymbolAddress(&ideg_ptr, g_ideg);
    cudaMemsetAsync(ideg_ptr, 0, NN * sizeof(int));

    k_deg_occ<<<(EE / 4 + T - 1) / T, T>>>((const int4*)dst);

    k_scan1<<<NB, 256>>>();
    k_scan3<<<NB, 256>>>();

    k_fill_init<<<FILL_BLOCKS + INIT_BLOCKS, T>>>((const int4*)src,
                                                  (const int4*)dst,
                                                  (const float4*)emb);

    int pull_blocks = (NN * 32 + T - 1) / T;    // one warp per row
    k_pull<<<pull_blocks, T>>>(0);              // y1
    k_pull<<<pull_blocks, T>>>(1);              // y2
    k_pull_fin<<<pull_blocks, T>>>((const float2*)emb, (float2*)out);

    (void)in_sizes; (void)n_in; (void)out_size;
}

// round 11
// speedup vs baseline: 1.5886x; 1.0976x over previous
#include <cuda_runtime.h>
#include <cuda_fp16.h>
#include <cstdint>

// LightGCN_75900662055226 — R11: pull gathers restructured to 8B lanes,
// 2 edges per warp-load (LDG.64), cross-half shfl merge. Prep unchanged.

#define NUM_USERS 100000
#define NUM_ITEMS 50000
#define NN (NUM_USERS + NUM_ITEMS)   // 150000
#define EE 2000000
#define DD 64
#define NL 3

#define NB ((NN + 255) / 256)        // 586 scan blocks

__device__ int            g_ideg[NN];       // integer in-degree
__device__ float          g_dinv[NN];       // 1/sqrt(deg) (0 if deg==0)
__device__ int            g_bsum[NB];       // per-block degree sums
__device__ int            g_rowptr[NN + 1]; // CSR row pointers (by dst)
__device__ unsigned short g_occ[EE];        // per-edge occurrence index in dst row
__device__ int            g_csr[EE];        // src only, sorted by dst
__device__ __half         g_yh[3][NN * DD]; // y0, y1, y2 (y = dinv .* x)

// ---------------------------------------------------------------------------

__global__ void k_deg_occ(const int4* __restrict__ dst4) {
    int i = blockIdx.x * blockDim.x + threadIdx.x;
    if (i < EE / 4) {
        int4 d = dst4[i];
        ushort4 o;
        o.x = (unsigned short)atomicAdd(&g_ideg[d.x], 1);
        o.y = (unsigned short)atomicAdd(&g_ideg[d.y], 1);
        o.z = (unsigned short)atomicAdd(&g_ideg[d.z], 1);
        o.w = (unsigned short)atomicAdd(&g_ideg[d.w], 1);
        reinterpret_cast<ushort4*>(g_occ)[i] = o;
    }
}

__global__ void k_scan1() {
    __shared__ int sh[256];
    int i = blockIdx.x * 256 + threadIdx.x;
    int v = (i < NN) ? g_ideg[i] : 0;
    sh[threadIdx.x] = v;
    __syncthreads();
    for (int s = 128; s > 0; s >>= 1) {
        if (threadIdx.x < s) sh[threadIdx.x] += sh[threadIdx.x + s];
        __syncthreads();
    }
    if (threadIdx.x == 0) g_bsum[blockIdx.x] = sh[0];
}

__global__ void k_scan3() {
    __shared__ int sh[256];
    __shared__ int blk_prefix;

    int acc = 0;
    for (int j = threadIdx.x; j < blockIdx.x; j += 256) acc += g_bsum[j];
    sh[threadIdx.x] = acc;
    __syncthreads();
    for (int s = 128; s > 0; s >>= 1) {
        if (threadIdx.x < s) sh[threadIdx.x] += sh[threadIdx.x + s];
        __syncthreads();
    }
    if (threadIdx.x == 0) blk_prefix = sh[0];
    __syncthreads();

    int i = blockIdx.x * 256 + threadIdx.x;
    int v = (i < NN) ? g_ideg[i] : 0;
    sh[threadIdx.x] = v;
    __syncthreads();
    for (int s = 1; s < 256; s <<= 1) {
        int t = (threadIdx.x >= s) ? sh[threadIdx.x - s] : 0;
        __syncthreads();
        sh[threadIdx.x] += t;
        __syncthreads();
    }
    if (i < NN) {
        int start = blk_prefix + sh[threadIdx.x] - v;   // exclusive
        g_rowptr[i] = start;
        g_dinv[i] = (v > 0) ? rsqrtf((float)v) : 0.0f;
    }
    if (i == 0) g_rowptr[NN] = EE;
}

#define FILL_BLOCKS ((EE / 4 + 255) / 256)
#define INIT_N4 (NN * DD / 4)
#define INIT_BLOCKS ((INIT_N4 + 255) / 256)

__global__ void k_fill_init(const int4* __restrict__ src4,
                            const int4* __restrict__ dst4,
                            const float4* __restrict__ emb4) {
    if (blockIdx.x < FILL_BLOCKS) {
        int i = blockIdx.x * blockDim.x + threadIdx.x;
        if (i >= EE / 4) return;
        int4 s = src4[i];
        int4 t = dst4[i];
        ushort4 o = reinterpret_cast<const ushort4*>(g_occ)[i];
        g_csr[g_rowptr[t.x] + o.x] = s.x;
        g_csr[g_rowptr[t.y] + o.y] = s.y;
        g_csr[g_rowptr[t.z] + o.z] = s.z;
        g_csr[g_rowptr[t.w] + o.w] = s.w;
    } else {
        int i = (blockIdx.x - FILL_BLOCKS) * blockDim.x + threadIdx.x;
        if (i >= INIT_N4) return;
        int node = i >> 4;
        float di = g_dinv[node];
        float4 v = emb4[i];
        __half2 h0 = __float22half2_rn(make_float2(v.x * di, v.y * di));
        __half2 h1 = __float22half2_rn(make_float2(v.z * di, v.w * di));
        __half2* yo = reinterpret_cast<__half2*>(g_yh[0]);
        yo[i * 2 + 0] = h0;
        yo[i * 2 + 1] = h1;
    }
}

// --- gather helper: accumulate one uint2 (4 halves) into 4 fp32 -------------

__device__ __forceinline__ void acc_u2(uint2 v, float& a0, float& a1,
                                       float& a2, float& a3) {
    __half2 hx = *reinterpret_cast<__half2*>(&v.x);
    __half2 hy = *reinterpret_cast<__half2*>(&v.y);
    float2 fx = __half22float2(hx);
    float2 fy = __half22float2(hy);
    a0 += fx.x; a1 += fx.y; a2 += fy.x; a3 += fy.y;
}

// --- pull: one warp per row; lane owns 8B of edge (j + lane/16)'s row -------
// 16 uint2 per 128B row: element = src*16 + sub.

__global__ void __launch_bounds__(256) k_pull(int lin) {
    __shared__ int ssrc[8][32];
    int wslot = threadIdx.x >> 5;
    int row = (blockIdx.x * blockDim.x + threadIdx.x) >> 5;
    int lane = threadIdx.x & 31;
    if (row >= NN) return;

    int half = lane >> 4;
    int sub = lane & 15;

    int beg = g_rowptr[row];
    int end = g_rowptr[row + 1];

    const uint2* __restrict__ yin = (const uint2*)g_yh[lin];
    float a0 = 0.f, a1 = 0.f, a2 = 0.f, a3 = 0.f;

    for (int base = beg; base < end; base += 32) {
        int e = base + lane;
        ssrc[wslot][lane] = (e < end) ? g_csr[e] : 0;
        __syncwarp();
        int cnt = min(32, end - base);

        int j = 0;
        for (; j + 8 <= cnt; j += 8) {
            int sA = ssrc[wslot][j + 0 + half];
            int sB = ssrc[wslot][j + 2 + half];
            int sC = ssrc[wslot][j + 4 + half];
            int sD = ssrc[wslot][j + 6 + half];
            uint2 vA = yin[sA * 16 + sub];
            uint2 vB = yin[sB * 16 + sub];
            uint2 vC = yin[sC * 16 + sub];
            uint2 vD = yin[sD * 16 + sub];
            acc_u2(vA, a0, a1, a2, a3);
            acc_u2(vB, a0, a1, a2, a3);
            acc_u2(vC, a0, a1, a2, a3);
            acc_u2(vD, a0, a1, a2, a3);
        }
        for (; j + 2 <= cnt; j += 2) {
            int s = ssrc[wslot][j + half];
            uint2 v = yin[s * 16 + sub];
            acc_u2(v, a0, a1, a2, a3);
        }
        if (j < cnt && half == 0) {            // odd leftover edge
            int s = ssrc[wslot][j];
            uint2 v = yin[s * 16 + sub];
            acc_u2(v, a0, a1, a2, a3);
        }
        __syncwarp();
    }

    // merge the two half-warp partials (lanes L and L+16 hold same columns)
    a0 += __shfl_xor_sync(0xffffffffu, a0, 16);
    a1 += __shfl_xor_sync(0xffffffffu, a1, 16);
    a2 += __shfl_xor_sync(0xffffffffu, a2, 16);
    a3 += __shfl_xor_sync(0xffffffffu, a3, 16);

    if (half == 0) {
        float di = g_dinv[row];
        float sc = di * di;
        __half2 h0 = __float22half2_rn(make_float2(a0 * sc, a1 * sc));
        __half2 h1 = __float22half2_rn(make_float2(a2 * sc, a3 * sc));
        uint2 w;
        w.x = *reinterpret_cast<uint32_t*>(&h0);
        w.y = *reinterpret_cast<uint32_t*>(&h1);
        ((uint2*)g_yh[lin + 1])[row * 16 + sub] = w;
    }
}

// --- final: same gather; out = (emb + (y1+y2)*sqrt(deg) + dinv*s3) / 4 ------

__global__ void __launch_bounds__(256) k_pull_fin(const float4* __restrict__ emb4,
                                                  float4* __restrict__ out4) {
    __shared__ int ssrc[8][32];
    int wslot = threadIdx.x >> 5;
    int row = (blockIdx.x * blockDim.x + threadIdx.x) >> 5;
    int lane = threadIdx.x & 31;
    if (row >= NN) return;

    int half = lane >> 4;
    int sub = lane & 15;

    int beg = g_rowptr[row];
    int end = g_rowptr[row + 1];

    const uint2* __restrict__ yin = (const uint2*)g_yh[2];
    float a0 = 0.f, a1 = 0.f, a2 = 0.f, a3 = 0.f;

    for (int base = beg; base < end; base += 32) {
        int e = base + lane;
        ssrc[wslot][lane] = (e < end) ? g_csr[e] : 0;
        __syncwarp();
        int cnt = min(32, end - base);

        int j = 0;
        for (; j + 8 <= cnt; j += 8) {
            int sA = ssrc[wslot][j + 0 + half];
            int sB = ssrc[wslot][j + 2 + half];
            int sC = ssrc[wslot][j + 4 + half];
            int sD = ssrc[wslot][j + 6 + half];
            uint2 vA = yin[sA * 16 + sub];
            uint2 vB = yin[sB * 16 + sub];
            uint2 vC = yin[sC * 16 + sub];
            uint2 vD = yin[sD * 16 + sub];
            acc_u2(vA, a0, a1, a2, a3);
            acc_u2(vB, a0, a1, a2, a3);
            acc_u2(vC, a0, a1, a2, a3);
            acc_u2(vD, a0, a1, a2, a3);
        }
        for (; j + 2 <= cnt; j += 2) {
            int s = ssrc[wslot][j + half];
            uint2 v = yin[s * 16 + sub];
            acc_u2(v, a0, a1, a2, a3);
        }
        if (j < cnt && half == 0) {
            int s = ssrc[wslot][j];
            uint2 v = yin[s * 16 + sub];
            acc_u2(v, a0, a1, a2, a3);
        }
        __syncwarp();
    }

    a0 += __shfl_xor_sync(0xffffffffu, a0, 16);
    a1 += __shfl_xor_sync(0xffffffffu, a1, 16);
    a2 += __shfl_xor_sync(0xffffffffu, a2, 16);
    a3 += __shfl_xor_sync(0xffffffffu, a3, 16);

    if (half == 0) {
        float di = g_dinv[row];
        float sq = (di > 0.0f) ? (1.0f / di) : 0.0f;   // sqrt(deg)
        int idx = row * 16 + sub;

        float4 e0 = emb4[idx];
        uint2 y1b = ((const uint2*)g_yh[1])[idx];
        uint2 y2b = ((const uint2*)g_yh[2])[idx];
        float2 y1lo = __half22float2(*reinterpret_cast<__half2*>(&y1b.x));
        float2 y1hi = __half22float2(*reinterpret_cast<__half2*>(&y1b.y));
        float2 y2lo = __half22float2(*reinterpret_cast<__half2*>(&y2b.x));
        float2 y2hi = __half22float2(*reinterpret_cast<__half2*>(&y2b.y));

        float4 o;
        o.x = (e0.x + (y1lo.x + y2lo.x) * sq + di * a0) * 0.25f;
        o.y = (e0.y + (y1lo.y + y2lo.y) * sq + di * a1) * 0.25f;
        o.z = (e0.z + (y1hi.x + y2hi.x) * sq + di * a2) * 0.25f;
        o.w = (e0.w + (y1hi.y + y2hi.y) * sq + di * a3) * 0.25f;
        out4[idx] = o;
    }
}

// ---------------------------------------------------------------------------

extern "C" void kernel_launch(void* const* d_in, const int* in_sizes, int n_in,
                              void* d_out, int out_size) {
    const int* edge = (const int*)d_in[0];      // [2, E] row-major
    const int* src = edge;
    const int* dst = edge + EE;
    const float* emb = (const float*)d_in[1];   // [N, 64]
    float* out = (float*)d_out;                 // [N, 64]

    const int T = 256;

    void* ideg_ptr = nullptr;
    cudaGetSymbolAddress(&ideg_ptr, g_ideg);
    cudaMemsetAsync(ideg_ptr, 0, NN * sizeof(int));

    k_deg_occ<<<(EE / 4 + T - 1) / T, T>>>((const int4*)dst);

    k_scan1<<<NB, 256>>>();
    k_scan3<<<NB, 256>>>();

    k_fill_init<<<FILL_BLOCKS + INIT_BLOCKS, T>>>((const int4*)src,
                                                  (const int4*)dst,
                                                  (const float4*)emb);

    int pull_blocks = (NN * 32 + T - 1) / T;    // one warp per row
    k_pull<<<pull_blocks, T>>>(0);              // y1
    k_pull<<<pull_blocks, T>>>(1);              // y2
    k_pull_fin<<<pull_blocks, T>>>((const float4*)emb, (float4*)out);

    (void)in_sizes; (void)n_in; (void)out_size;
}